// round 16
// baseline (speedup 1.0000x reference)
#include <cuda_runtime.h>
#include <cuda_fp16.h>
#include <math.h>
#include <stdint.h>

#define M_TOT 32768
#define K1 2304
#define K2 1024

// ----------------------------- scratch ---------------------------------------
__device__ __half g_vh[(size_t)K1 * M_TOT];         // deform samples fp16, (K1, M)
__device__ __half g_h1h[(size_t)8 * 256 * 4096];    // stage-1 out, fp16 (b,c,pix)
__device__ float  g_offmask[32u * M_TOT];           // offset/mask conv out (27 used rows)
__device__ __half g_Wh[256 * K1];                   // w_reg fp16 (N,K)
__device__ __half g_Bomh[32 * K1];                  // offset+mask weights (pad 32)
__device__ float  g_biasom[32];
__device__ __half g_B2h[4 * 256 * K2];              // convT per-parity (N,K)

// ----------------------------- helpers ---------------------------------------
__device__ __forceinline__ uint32_t smem_u32(const void* p) {
    uint32_t a;
    asm("{ .reg .u64 t; cvta.to.shared.u64 t, %1; cvt.u32.u64 %0, t; }" : "=r"(a) : "l"(p));
    return a;
}
__device__ __forceinline__ void ldsm4(uint32_t* r, uint32_t addr) {
    asm volatile("ldmatrix.sync.aligned.m8n8.x4.shared.b16 {%0,%1,%2,%3}, [%4];"
                 : "=r"(r[0]), "=r"(r[1]), "=r"(r[2]), "=r"(r[3]) : "r"(addr));
}
__device__ __forceinline__ void ldsm4t(uint32_t* r, uint32_t addr) {
    asm volatile("ldmatrix.sync.aligned.m8n8.x4.trans.shared.b16 {%0,%1,%2,%3}, [%4];"
                 : "=r"(r[0]), "=r"(r[1]), "=r"(r[2]), "=r"(r[3]) : "r"(addr));
}
__device__ __forceinline__ void mma16816(float* c, const uint32_t* a, const uint32_t* b) {
    asm volatile(
        "mma.sync.aligned.m16n8k16.row.col.f32.f16.f16.f32 "
        "{%0,%1,%2,%3}, {%4,%5,%6,%7}, {%8,%9}, {%0,%1,%2,%3};"
        : "+f"(c[0]), "+f"(c[1]), "+f"(c[2]), "+f"(c[3])
        : "r"(a[0]), "r"(a[1]), "r"(a[2]), "r"(a[3]), "r"(b[0]), "r"(b[1]));
}
__device__ __forceinline__ void cp16(uint32_t dst, const void* src) {
    asm volatile("cp.async.ca.shared.global [%0], [%1], 16;" :: "r"(dst), "l"(src));
}
__device__ __forceinline__ void cp_commit() { asm volatile("cp.async.commit_group;"); }
__device__ __forceinline__ void cp_wait0() { asm volatile("cp.async.wait_group 0;"); }
__device__ __forceinline__ void stcs(float* p, float v) {
    asm volatile("st.global.cs.f32 [%0], %1;" :: "l"(p), "f"(v));
}

// ----------------------------- weight packing --------------------------------
__global__ void pack_w_kernel(const float* __restrict__ w_reg, const float* __restrict__ w_off,
                              const float* __restrict__ b_off, const float* __restrict__ w_mod,
                              const float* __restrict__ b_mod, const float* __restrict__ w_up) {
    int i = blockIdx.x * 256 + threadIdx.x;
    if (i < 256 * K1) g_Wh[i] = __float2half(w_reg[i]);
    if (i < 32 * K1) {
        int n = i / K1;
        float v = 0.f;
        if (n < 18) v = w_off[i];
        else if (n < 27) v = w_mod[i - 18 * K1];
        g_Bomh[i] = __float2half(v);
    }
    if (i < 32) g_biasom[i] = (i < 18) ? b_off[i] : ((i < 27) ? b_mod[i - 18] : 0.f);
    if (i < 4 * 256 * K2) {
        int k = i & 1023, n = (i >> 10) & 255, p = i >> 18;
        int c = k >> 2, t = k & 3, ty = t >> 1, tx = t & 1;
        int py = p >> 1, px = p & 1;
        int kh = py ? (ty ? 2 : 0) : (ty ? 3 : 1);
        int kw = px ? (tx ? 2 : 0) : (tx ? 3 : 1);
        g_B2h[i] = __float2half(w_up[(c << 12) + (n << 4) + (kh << 2) + kw]);
    }
}

// ----------------------------- deform sampling -------------------------------
__global__ void build_v_kernel(const float* __restrict__ x) {
    int m = blockIdx.x * 256 + threadIdx.x;
    int k = blockIdx.y;
    int b = m >> 12, pix = m & 4095, h = pix >> 6, w = pix & 63;
    float oy = g_offmask[(size_t)(2 * k) * M_TOT + m];
    float ox = g_offmask[(size_t)(2 * k + 1) * M_TOT + m];
    float mr = g_offmask[(size_t)(18 + k) * M_TOT + m];
    float mask = 2.f / (1.f + expf(-mr));
    int ky = k / 3, kx = k % 3;
    float py = (float)(h - 1 + ky) + oy;
    float px = (float)(w - 1 + kx) + ox;
    float y0f = floorf(py), x0f = floorf(px);
    float wy1 = py - y0f, wx1 = px - x0f;
    float wy0 = 1.f - wy1, wx0 = 1.f - wx1;
    int y0 = (int)y0f, x0 = (int)x0f, y1 = y0 + 1, x1 = x0 + 1;
    bool vy0 = (y0 >= 0 && y0 < 64), vy1 = (y1 >= 0 && y1 < 64);
    bool vx0 = (x0 >= 0 && x0 < 64), vx1 = (x1 >= 0 && x1 < 64);
    int yc0 = min(max(y0, 0), 63), yc1 = min(max(y1, 0), 63);
    int xc0 = min(max(x0, 0), 63), xc1 = min(max(x1, 0), 63);
    int o00 = (yc0 << 6) + xc0, o01 = (yc0 << 6) + xc1;
    int o10 = (yc1 << 6) + xc0, o11 = (yc1 << 6) + xc1;
    float w00 = wy0 * wx0 * ((vy0 && vx0) ? mask : 0.f);
    float w01 = wy0 * wx1 * ((vy0 && vx1) ? mask : 0.f);
    float w10 = wy1 * wx0 * ((vy1 && vx0) ? mask : 0.f);
    float w11 = wy1 * wx1 * ((vy1 && vx1) ? mask : 0.f);
    const float* xb = x + ((size_t)b << 20);
#pragma unroll 4
    for (int c = 0; c < 256; c++) {
        const float* xc = xb + (c << 12);
        float v = w00 * xc[o00] + w01 * xc[o01] + w10 * xc[o10] + w11 * xc[o11];
        g_vh[(size_t)(c * 9 + k) * M_TOT + m] = __float2half(v);
    }
}

// ----------------------------- unified HMMA GEMM ------------------------------
// C(M=32768, N) = A(K,M)^T x B(N,K)^T, fp16 in, fp32 accum.  K-chunk = 64.
// 2-stage pipeline, fills issued before the MMA phase.
// A SMEM: K-major, 64 k-rows x 128 m-cols, 272B row stride.
// B SMEM: N-major, NTILE n-rows x 64 k-cols, 144B row stride.
// ASRC: 0 = fp16 plane g_vh (cp.async); 1 = im2col gather from x (fp32);
//       2 = tap gather from fp16 h1 (blockIdx.x = parity).
// EPI:  0 = +bias -> (N,M) fp32; 1 = BN+ReLU -> fp16 h1; 2 = BN+ReLU parity scatter.
template <int THREADS, int NTILE, int WN, int ASRC, int EPI>
__global__ __launch_bounds__(512, 1) void mma_gemm(
    const void* __restrict__ Asrc, const __half* __restrict__ Bhg,
    void* __restrict__ Cout, int K,
    const float* __restrict__ p0, const float* __restrict__ p1,
    const float* __restrict__ p2, const float* __restrict__ p3) {
    constexpr int NWARPS = THREADS / 32;
    constexpr int WM = NWARPS / WN;
    constexpr int WARP_M = 128 / WM;
    constexpr int WARP_N = NTILE / WN;
    constexpr int MT = WARP_M / 16;
    constexpr int NTG = WARP_N / 16;
    constexpr int NT = NTG * 2;
    constexpr int A_PLANE = 64 * 272;            // 17408
    constexpr int B_PLANE = NTILE * 144;
    constexpr int STAGE = A_PLANE + B_PLANE;
    constexpr int ACH = 1024;                    // A 16B cp.async chunks per stage
    constexpr int AJ = ACH / THREADS;
    constexpr int GCH = 2048;                    // A gather groups (4 m each)
    constexpr int GJ = GCH / THREADS;
    constexpr int BCH = NTILE * 8;               // B 16B cp.async chunks per stage
    constexpr int BJ = (BCH + THREADS - 1) / THREADS;

    extern __shared__ char sb[];
    uint32_t sbase = smem_u32(sb);

    int t = threadIdx.x, warp = t >> 5, lane = t & 31;
    int par = (ASRC == 2) ? blockIdx.x : 0;
    int m0 = blockIdx.y * 128;
    int py = par >> 1, px = par & 1;

    const __half* Bh = Bhg + (size_t)par * 256 * K;

    int mw = (warp / WN) * WARP_M;
    int nw = (warp % WN) * WARP_N;

    // ldmatrix lane addressing
    int g = lane >> 3;
    int a_k = (lane & 7) + ((g >> 1) << 3);
    int a_moff = (g & 1) << 3;
    uint32_t aBase = (uint32_t)(a_k * 272 + (mw + a_moff) * 2);
    int b_row = (lane & 7) | ((lane >> 4) << 3);
    int b_kh = ((lane >> 3) & 1) << 3;
    uint32_t bBase = (uint32_t)(A_PLANE + (nw + b_row) * 144 + b_kh * 2);

    float acc[MT][NT][4];
#pragma unroll
    for (int i = 0; i < MT; i++)
#pragma unroll
        for (int j = 0; j < NT; j++)
#pragma unroll
            for (int e = 0; e < 4; e++) acc[i][j][e] = 0.f;

    int nch = K >> 6;

    // ---- A fill into stage s for chunk cc (branch-free predicated gathers)
    auto fillA = [&](int cc, int s) {
        int k0 = cc << 6;
        if (ASRC == 0) {
            const __half* vh = (const __half*)Asrc;
            uint32_t base = sbase + s * STAGE;
#pragma unroll
            for (int j = 0; j < AJ; j++) {
                int idx = t + j * THREADS;
                int k = idx >> 4, q = idx & 15;
                const __half* src = vh + (size_t)(k0 + k) * M_TOT + m0 + q * 8;
                cp16(base + k * 272 + q * 16, src);
            }
        } else {
            char* sA = sb + s * STAGE;
#pragma unroll
            for (int j = 0; j < GJ; j++) {
                int gi = t + j * THREADS;       // groups of 4 m
                int k = gi >> 5, m4 = (gi & 31) << 2;
                int kk = k0 + k;
                int off = k * 272 + m4 * 2;
                if (ASRC == 1) {
                    int c = kk / 9, tt = kk - 9 * c, ty = tt / 3, tx = tt - 3 * ty;
                    const float* xg = (const float*)Asrc;
                    uint32_t hi[4];
#pragma unroll
                    for (int e = 0; e < 4; e++) {
                        int gm = m0 + m4 + e;
                        int b = gm >> 12, pix = gm & 4095, ii = pix >> 6, jj = pix & 63;
                        int y = ii + ty - 1, xx = jj + tx - 1;
                        bool ok = ((unsigned)y < 64u) && ((unsigned)xx < 64u);
                        float f = ok ? xg[(((size_t)(b * 256 + c)) << 12) + (y << 6) + xx] : 0.f;
                        hi[e] = __half_as_ushort(__float2half(f));
                    }
                    *(uint2*)(sA + off) =
                        make_uint2(hi[0] | (hi[1] << 16), hi[2] | (hi[3] << 16));
                } else {
                    int c = kk >> 2, tt = kk & 3, ty = tt >> 1, tx = tt & 1;
                    const __half* hp = (const __half*)Asrc;
                    uint32_t w[4];
#pragma unroll
                    for (int e = 0; e < 4; e++) {
                        int gm = m0 + m4 + e;
                        int b = gm >> 12, pix = gm & 4095, ii = pix >> 6, jj = pix & 63;
                        int r = ii + py - ty, cx = jj + px - tx;
                        bool ok = ((unsigned)r < 64u) && ((unsigned)cx < 64u);
                        w[e] = ok
                            ? (uint32_t)__half_as_ushort(
                                  hp[(((size_t)(b * 256 + c)) << 12) + (r << 6) + cx])
                            : 0u;
                    }
                    *(uint2*)(sA + off) =
                        make_uint2(w[0] | (w[1] << 16), w[2] | (w[3] << 16));
                }
            }
        }
    };
    // ---- B fill via cp.async
    auto fillB = [&](int cc, int s) {
        int k0 = cc << 6;
        uint32_t base = sbase + s * STAGE + A_PLANE;
#pragma unroll
        for (int j = 0; j < BJ; j++) {
            int idx = t + j * THREADS;
            if (idx < BCH) {
                int r = idx >> 3, q = idx & 7;
                const __half* src = Bh + (size_t)r * K + k0 + q * 8;
                cp16(base + r * 144 + q * 16, src);
            }
        }
    };
    // ---- MMA on stage s (4 k16 steps)
    auto domma = [&](int s) {
        uint32_t sA0 = sbase + s * STAGE;
#pragma unroll
        for (int ks = 0; ks < 4; ks++) {
            uint32_t aoff = sA0 + aBase + ks * 4352;
            uint32_t boff = sA0 + bBase + ks * 32;
            uint32_t ah[MT][4], bh[NTG][4];
#pragma unroll
            for (int mt = 0; mt < MT; mt++) ldsm4t(ah[mt], aoff + mt * 32);
#pragma unroll
            for (int bg = 0; bg < NTG; bg++) ldsm4(bh[bg], boff + bg * 2304);
#pragma unroll
            for (int mt = 0; mt < MT; mt++)
#pragma unroll
                for (int nt = 0; nt < NT; nt++)
                    mma16816(acc[mt][nt], ah[mt], &bh[nt >> 1][(nt & 1) * 2]);
        }
    };

    // ---- prologue: fill stage 0
    fillA(0, 0);
    fillB(0, 0);
    cp_commit();
    cp_wait0();
    __syncthreads();

    for (int c = 0; c < nch; c++) {
        int s = c & 1;
        if (c + 1 < nch) {
            fillA(c + 1, s ^ 1);
            fillB(c + 1, s ^ 1);
            cp_commit();
        }
        domma(s);
        cp_wait0();
        __syncthreads();
    }

    // ---------------- epilogue ----------------
    int gi = lane >> 2, ci = (lane & 3) << 1;
#pragma unroll
    for (int mt = 0; mt < MT; mt++) {
#pragma unroll
        for (int nt = 0; nt < NT; nt++) {
            int nB = nw + nt * 8 + ci;
            int mA = m0 + mw + mt * 16 + gi;
#pragma unroll
            for (int e = 0; e < 4; e++) {
                int m = mA + ((e >> 1) << 3);
                int nn = nB + (e & 1);
                float v = acc[mt][nt][e];
                if (EPI == 0) {
                    if (nn < 27)
                        ((float*)Cout)[(size_t)nn * M_TOT + m] = v + p0[nn];
                } else {
                    float sc = p0[nn] * rsqrtf(p3[nn] + 1e-5f);
                    float r = fmaxf(v * sc + (p1[nn] - p2[nn] * sc), 0.f);
                    int b = m >> 12, pix = m & 4095;
                    if (EPI == 1) {
                        ((__half*)Cout)[(((size_t)(b * 256 + nn)) << 12) + pix] =
                            __float2half(r);
                    } else {
                        int i2 = pix >> 6, j2 = pix & 63;
                        stcs(&((float*)Cout)[(((size_t)((b * 256 + nn) * 128 +
                              2 * i2 + py)) << 7) + 2 * j2 + px], r);
                    }
                }
            }
        }
    }
}

// -----------------------------------------------------------------------------
extern "C" void kernel_launch(void* const* d_in, const int* in_sizes, int n_in,
                              void* d_out, int out_size) {
    const float* x     = (const float*)d_in[0];
    const float* w_off = (const float*)d_in[1];
    const float* b_off = (const float*)d_in[2];
    const float* w_mod = (const float*)d_in[3];
    const float* b_mod = (const float*)d_in[4];
    const float* w_reg = (const float*)d_in[5];
    const float* bn1_g = (const float*)d_in[6];
    const float* bn1_b = (const float*)d_in[7];
    const float* bn1_m = (const float*)d_in[8];
    const float* bn1_v = (const float*)d_in[9];
    const float* w_up  = (const float*)d_in[10];
    const float* bn2_g = (const float*)d_in[11];
    const float* bn2_b = (const float*)d_in[12];
    const float* bn2_m = (const float*)d_in[13];
    const float* bn2_v = (const float*)d_in[14];
    float* out = (float*)d_out;

    __half *vh, *h1h, *Wh, *Bomh, *B2h;
    float *om, *biasom;
    cudaGetSymbolAddress((void**)&vh,     g_vh);
    cudaGetSymbolAddress((void**)&h1h,    g_h1h);
    cudaGetSymbolAddress((void**)&om,     g_offmask);
    cudaGetSymbolAddress((void**)&biasom, g_biasom);
    cudaGetSymbolAddress((void**)&Wh,     g_Wh);
    cudaGetSymbolAddress((void**)&Bomh,   g_Bomh);
    cudaGetSymbolAddress((void**)&B2h,    g_B2h);

    const int STAGE32  = 17408 + 32 * 144;        // 22016
    const int STAGE256 = 17408 + 256 * 144;       // 54272
    const int smem32  = 2 * STAGE32;              // 44032
    const int smem256 = 2 * STAGE256;             // 108544
    cudaFuncSetAttribute((const void*)mma_gemm<256, 32, 2, 1, 0>,
                         cudaFuncAttributeMaxDynamicSharedMemorySize, smem32);
    cudaFuncSetAttribute((const void*)mma_gemm<512, 256, 8, 0, 1>,
                         cudaFuncAttributeMaxDynamicSharedMemorySize, smem256);
    cudaFuncSetAttribute((const void*)mma_gemm<512, 256, 8, 2, 2>,
                         cudaFuncAttributeMaxDynamicSharedMemorySize, smem256);

    // weight packing
    pack_w_kernel<<<4096, 256>>>(w_reg, w_off, b_off, w_mod, b_mod, w_up);

    // stage 0: offset/mask conv (im2col fused into GEMM A-fill)
    mma_gemm<256, 32, 2, 1, 0><<<dim3(1, 256), 256, smem32>>>(
        x, Bomh, om, K1, biasom, nullptr, nullptr, nullptr);

    // stage 1: deform sampling + deform GEMM (+BN1+ReLU -> fp16 h1), full N tile
    build_v_kernel<<<dim3(128, 9), 256>>>(x);
    mma_gemm<512, 256, 8, 0, 1><<<dim3(1, 256), 512, smem256>>>(
        vh, Wh, h1h, K1, bn1_g, bn1_b, bn1_m, bn1_v);

    // stage 2: conv-transpose from fp16 h1, full N tile, blockIdx.x = parity
    mma_gemm<512, 256, 8, 2, 2><<<dim3(4, 256), 512, smem256>>>(
        h1h, B2h, out, K2, bn2_g, bn2_b, bn2_m, bn2_v);
}

// round 17
// speedup vs baseline: 1.4499x; 1.4499x over previous
#include <cuda_runtime.h>
#include <cuda_fp16.h>
#include <math.h>
#include <stdint.h>

#define M_TOT 32768
#define K1 2304
#define K2 1024

// ----------------------------- scratch ---------------------------------------
__device__ __half g_vh[(size_t)K1 * M_TOT];         // deform samples fp16, (K1, M)
__device__ __half g_h1h[(size_t)8 * 256 * 4096];    // stage-1 out, fp16 (b,c,pix)
__device__ float  g_offmask[32u * M_TOT];           // offset/mask conv out (27 used rows)
__device__ __half g_Wh[256 * K1];                   // w_reg fp16 (N,K)
__device__ __half g_Bomh[32 * K1];                  // offset+mask weights (pad 32)
__device__ float  g_biasom[32];
__device__ __half g_B2h[4 * 256 * K2];              // convT per-parity (N,K)

// ----------------------------- helpers ---------------------------------------
__device__ __forceinline__ uint32_t smem_u32(const void* p) {
    uint32_t a;
    asm("{ .reg .u64 t; cvta.to.shared.u64 t, %1; cvt.u32.u64 %0, t; }" : "=r"(a) : "l"(p));
    return a;
}
__device__ __forceinline__ void ldsm4(uint32_t* r, uint32_t addr) {
    asm volatile("ldmatrix.sync.aligned.m8n8.x4.shared.b16 {%0,%1,%2,%3}, [%4];"
                 : "=r"(r[0]), "=r"(r[1]), "=r"(r[2]), "=r"(r[3]) : "r"(addr));
}
__device__ __forceinline__ void ldsm4t(uint32_t* r, uint32_t addr) {
    asm volatile("ldmatrix.sync.aligned.m8n8.x4.trans.shared.b16 {%0,%1,%2,%3}, [%4];"
                 : "=r"(r[0]), "=r"(r[1]), "=r"(r[2]), "=r"(r[3]) : "r"(addr));
}
__device__ __forceinline__ void mma16816(float* c, const uint32_t* a, const uint32_t* b) {
    asm volatile(
        "mma.sync.aligned.m16n8k16.row.col.f32.f16.f16.f32 "
        "{%0,%1,%2,%3}, {%4,%5,%6,%7}, {%8,%9}, {%0,%1,%2,%3};"
        : "+f"(c[0]), "+f"(c[1]), "+f"(c[2]), "+f"(c[3])
        : "r"(a[0]), "r"(a[1]), "r"(a[2]), "r"(a[3]), "r"(b[0]), "r"(b[1]));
}
__device__ __forceinline__ void cp16(uint32_t dst, const void* src) {
    asm volatile("cp.async.ca.shared.global [%0], [%1], 16;" :: "r"(dst), "l"(src));
}
__device__ __forceinline__ void cp_commit() { asm volatile("cp.async.commit_group;"); }
__device__ __forceinline__ void cp_wait0() { asm volatile("cp.async.wait_group 0;"); }
__device__ __forceinline__ void stcs(float* p, float v) {
    asm volatile("st.global.cs.f32 [%0], %1;" :: "l"(p), "f"(v));
}

// ----------------------------- weight packing --------------------------------
__global__ void pack_w_kernel(const float* __restrict__ w_reg, const float* __restrict__ w_off,
                              const float* __restrict__ b_off, const float* __restrict__ w_mod,
                              const float* __restrict__ b_mod, const float* __restrict__ w_up) {
    int i = blockIdx.x * 256 + threadIdx.x;
    if (i < 256 * K1) g_Wh[i] = __float2half(w_reg[i]);
    if (i < 32 * K1) {
        int n = i / K1;
        float v = 0.f;
        if (n < 18) v = w_off[i];
        else if (n < 27) v = w_mod[i - 18 * K1];
        g_Bomh[i] = __float2half(v);
    }
    if (i < 32) g_biasom[i] = (i < 18) ? b_off[i] : ((i < 27) ? b_mod[i - 18] : 0.f);
    if (i < 4 * 256 * K2) {
        int k = i & 1023, n = (i >> 10) & 255, p = i >> 18;
        int c = k >> 2, t = k & 3, ty = t >> 1, tx = t & 1;
        int py = p >> 1, px = p & 1;
        int kh = py ? (ty ? 2 : 0) : (ty ? 3 : 1);
        int kw = px ? (tx ? 2 : 0) : (tx ? 3 : 1);
        g_B2h[i] = __float2half(w_up[(c << 12) + (n << 4) + (kh << 2) + kw]);
    }
}

// ----------------------------- deform sampling -------------------------------
__global__ void build_v_kernel(const float* __restrict__ x) {
    int m = blockIdx.x * 256 + threadIdx.x;
    int k = blockIdx.y;
    int b = m >> 12, pix = m & 4095, h = pix >> 6, w = pix & 63;
    float oy = g_offmask[(size_t)(2 * k) * M_TOT + m];
    float ox = g_offmask[(size_t)(2 * k + 1) * M_TOT + m];
    float mr = g_offmask[(size_t)(18 + k) * M_TOT + m];
    float mask = 2.f / (1.f + expf(-mr));
    int ky = k / 3, kx = k % 3;
    float py = (float)(h - 1 + ky) + oy;
    float px = (float)(w - 1 + kx) + ox;
    float y0f = floorf(py), x0f = floorf(px);
    float wy1 = py - y0f, wx1 = px - x0f;
    float wy0 = 1.f - wy1, wx0 = 1.f - wx1;
    int y0 = (int)y0f, x0 = (int)x0f, y1 = y0 + 1, x1 = x0 + 1;
    bool vy0 = (y0 >= 0 && y0 < 64), vy1 = (y1 >= 0 && y1 < 64);
    bool vx0 = (x0 >= 0 && x0 < 64), vx1 = (x1 >= 0 && x1 < 64);
    int yc0 = min(max(y0, 0), 63), yc1 = min(max(y1, 0), 63);
    int xc0 = min(max(x0, 0), 63), xc1 = min(max(x1, 0), 63);
    int o00 = (yc0 << 6) + xc0, o01 = (yc0 << 6) + xc1;
    int o10 = (yc1 << 6) + xc0, o11 = (yc1 << 6) + xc1;
    float w00 = wy0 * wx0 * ((vy0 && vx0) ? mask : 0.f);
    float w01 = wy0 * wx1 * ((vy0 && vx1) ? mask : 0.f);
    float w10 = wy1 * wx0 * ((vy1 && vx0) ? mask : 0.f);
    float w11 = wy1 * wx1 * ((vy1 && vx1) ? mask : 0.f);
    const float* xb = x + ((size_t)b << 20);
    for (int c = 0; c < 256; c++) {
        const float* xc = xb + (c << 12);
        float v = w00 * xc[o00] + w01 * xc[o01] + w10 * xc[o10] + w11 * xc[o11];
        g_vh[(size_t)(c * 9 + k) * M_TOT + m] = __float2half(v);
    }
}

// ----------------------------- unified HMMA GEMM ------------------------------
// C(M=32768, N) = A(K,M)^T x B(N,K)^T, fp16 in, fp32 accum.  K-chunk = 64.
// 2-stage pipeline, fills issued before the MMA phase (R11 structure).
// A SMEM: K-major, 64 k-rows x 128 m-cols, 272B row stride.
// B SMEM: N-major, NTILE n-rows x 64 k-cols, 144B row stride.
// ASRC: 0 = fp16 plane g_vh (cp.async); 1 = im2col gather from x (fp32);
//       2 = tap gather from fp16 h1.
// EPI:  0 = +bias -> (N,M) fp32; 1 = BN+ReLU -> fp16 h1; 2 = BN+ReLU parity scatter.
template <int NTILE, int ASRC, int EPI>
__global__ __launch_bounds__(256, 2) void mma_gemm(
    const void* __restrict__ Asrc, const __half* __restrict__ Bhg,
    void* __restrict__ Cout, int K,
    const float* __restrict__ p0, const float* __restrict__ p1,
    const float* __restrict__ p2, const float* __restrict__ p3) {
    constexpr int WN = (NTILE >= 128) ? 4 : 2;
    constexpr int WM = 8 / WN;
    constexpr int WARP_M = 128 / WM;
    constexpr int WARP_N = NTILE / WN;
    constexpr int MT = WARP_M / 16;
    constexpr int NTG = WARP_N / 16;
    constexpr int NT = NTG * 2;
    constexpr int A_PLANE = 64 * 272;            // 17408
    constexpr int B_PLANE = NTILE * 144;
    constexpr int STAGE = A_PLANE + B_PLANE;
    constexpr int BCH = NTILE * 8;               // cp.async 16B chunks per stage (B)
    constexpr int BJ = (BCH + 255) / 256;

    extern __shared__ char sb[];
    uint32_t sbase = smem_u32(sb);

    int t = threadIdx.x, warp = t >> 5, lane = t & 31;
    int ntile_id, par;
    if (ASRC == 2) { par = blockIdx.x >> 1; ntile_id = blockIdx.x & 1; }
    else { par = 0; ntile_id = blockIdx.x; }
    int nbase = ntile_id * NTILE;
    int m0 = blockIdx.y * 128;
    int py = par >> 1, px = par & 1;

    const __half* Bh = Bhg + ((size_t)par * 256 + nbase) * K;

    int mw = (warp / WN) * WARP_M;
    int nw = (warp % WN) * WARP_N;

    // ldmatrix lane addressing
    int g = lane >> 3;
    int a_k = (lane & 7) + ((g >> 1) << 3);
    int a_moff = (g & 1) << 3;
    uint32_t aBase = (uint32_t)(a_k * 272 + (mw + a_moff) * 2);
    int b_row = (lane & 7) | ((lane >> 4) << 3);
    int b_kh = ((lane >> 3) & 1) << 3;
    uint32_t bBase = (uint32_t)(A_PLANE + (nw + b_row) * 144 + b_kh * 2);

    float acc[MT][NT][4];
#pragma unroll
    for (int i = 0; i < MT; i++)
#pragma unroll
        for (int j = 0; j < NT; j++)
#pragma unroll
            for (int e = 0; e < 4; e++) acc[i][j][e] = 0.f;

    int nch = K >> 6;

    // ---- A fill into stage s for chunk cc (branch-free predicated gathers)
    auto fillA = [&](int cc, int s) {
        int k0 = cc << 6;
        if (ASRC == 0) {
            const __half* vh = (const __half*)Asrc;
            uint32_t base = sbase + s * STAGE;
#pragma unroll
            for (int j = 0; j < 4; j++) {
                int idx = t + j * 256;          // 1024 chunks
                int k = idx >> 4, q = idx & 15;
                const __half* src = vh + (size_t)(k0 + k) * M_TOT + m0 + q * 8;
                cp16(base + k * 272 + q * 16, src);
            }
        } else {
            char* sA = sb + s * STAGE;
#pragma unroll
            for (int j = 0; j < 8; j++) {
                int gi = t + j * 256;           // 2048 groups of 4 m
                int k = gi >> 5, m4 = (gi & 31) << 2;
                int kk = k0 + k;
                int off = k * 272 + m4 * 2;
                if (ASRC == 1) {
                    int c = kk / 9, tt = kk - 9 * c, ty = tt / 3, tx = tt - 3 * ty;
                    const float* xg = (const float*)Asrc;
                    uint32_t hi[4];
#pragma unroll
                    for (int e = 0; e < 4; e++) {
                        int gm = m0 + m4 + e;
                        int b = gm >> 12, pix = gm & 4095, ii = pix >> 6, jj = pix & 63;
                        int y = ii + ty - 1, xx = jj + tx - 1;
                        bool ok = ((unsigned)y < 64u) && ((unsigned)xx < 64u);
                        float f = ok ? xg[(((size_t)(b * 256 + c)) << 12) + (y << 6) + xx] : 0.f;
                        hi[e] = __half_as_ushort(__float2half(f));
                    }
                    *(uint2*)(sA + off) =
                        make_uint2(hi[0] | (hi[1] << 16), hi[2] | (hi[3] << 16));
                } else {
                    int c = kk >> 2, tt = kk & 3, ty = tt >> 1, tx = tt & 1;
                    const __half* hp = (const __half*)Asrc;
                    uint32_t w[4];
#pragma unroll
                    for (int e = 0; e < 4; e++) {
                        int gm = m0 + m4 + e;
                        int b = gm >> 12, pix = gm & 4095, ii = pix >> 6, jj = pix & 63;
                        int r = ii + py - ty, cx = jj + px - tx;
                        bool ok = ((unsigned)r < 64u) && ((unsigned)cx < 64u);
                        w[e] = ok
                            ? (uint32_t)__half_as_ushort(
                                  hp[(((size_t)(b * 256 + c)) << 12) + (r << 6) + cx])
                            : 0u;
                    }
                    *(uint2*)(sA + off) =
                        make_uint2(w[0] | (w[1] << 16), w[2] | (w[3] << 16));
                }
            }
        }
    };
    // ---- B fill via cp.async
    auto fillB = [&](int cc, int s) {
        int k0 = cc << 6;
        uint32_t base = sbase + s * STAGE + A_PLANE;
#pragma unroll
        for (int j = 0; j < BJ; j++) {
            int idx = t + j * 256;
            if (idx < BCH) {
                int r = idx >> 3, q = idx & 7;
                const __half* src = Bh + (size_t)r * K + k0 + q * 8;
                cp16(base + r * 144 + q * 16, src);
            }
        }
    };
    // ---- MMA on stage s (4 k16 steps)
    auto domma = [&](int s) {
        uint32_t sA0 = sbase + s * STAGE;
#pragma unroll
        for (int ks = 0; ks < 4; ks++) {
            uint32_t aoff = sA0 + aBase + ks * 4352;
            uint32_t boff = sA0 + bBase + ks * 32;
            uint32_t ah[MT][4], bh[NTG][4];
#pragma unroll
            for (int mt = 0; mt < MT; mt++) ldsm4t(ah[mt], aoff + mt * 32);
#pragma unroll
            for (int bg = 0; bg < NTG; bg++) ldsm4(bh[bg], boff + bg * 2304);
#pragma unroll
            for (int mt = 0; mt < MT; mt++)
#pragma unroll
                for (int nt = 0; nt < NT; nt++)
                    mma16816(acc[mt][nt], ah[mt], &bh[nt >> 1][(nt & 1) * 2]);
        }
    };

    // ---- prologue: fill stage 0
    fillA(0, 0);
    fillB(0, 0);
    cp_commit();
    cp_wait0();
    __syncthreads();

    for (int c = 0; c < nch; c++) {
        int s = c & 1;
        if (c + 1 < nch) {
            fillA(c + 1, s ^ 1);
            fillB(c + 1, s ^ 1);
            cp_commit();
        }
        domma(s);
        cp_wait0();
        __syncthreads();
    }

    // ---------------- epilogue ----------------
    int gi = lane >> 2, ci = (lane & 3) << 1;
#pragma unroll
    for (int mt = 0; mt < MT; mt++) {
#pragma unroll
        for (int nt = 0; nt < NT; nt++) {
            int nB = nbase + nw + nt * 8 + ci;
            int mA = m0 + mw + mt * 16 + gi;
#pragma unroll
            for (int e = 0; e < 4; e++) {
                int m = mA + ((e >> 1) << 3);
                int nn = nB + (e & 1);
                float v = acc[mt][nt][e];
                if (EPI == 0) {
                    if (nn < 27)
                        ((float*)Cout)[(size_t)nn * M_TOT + m] = v + p0[nn];
                } else {
                    float sc = p0[nn] * rsqrtf(p3[nn] + 1e-5f);
                    float r = fmaxf(v * sc + (p1[nn] - p2[nn] * sc), 0.f);
                    int b = m >> 12, pix = m & 4095;
                    if (EPI == 1) {
                        ((__half*)Cout)[(((size_t)(b * 256 + nn)) << 12) + pix] =
                            __float2half(r);
                    } else {
                        int i2 = pix >> 6, j2 = pix & 63;
                        stcs(&((float*)Cout)[(((size_t)((b * 256 + nn) * 128 +
                              2 * i2 + py)) << 7) + 2 * j2 + px], r);
                    }
                }
            }
        }
    }
}

// -----------------------------------------------------------------------------
extern "C" void kernel_launch(void* const* d_in, const int* in_sizes, int n_in,
                              void* d_out, int out_size) {
    const float* x     = (const float*)d_in[0];
    const float* w_off = (const float*)d_in[1];
    const float* b_off = (const float*)d_in[2];
    const float* w_mod = (const float*)d_in[3];
    const float* b_mod = (const float*)d_in[4];
    const float* w_reg = (const float*)d_in[5];
    const float* bn1_g = (const float*)d_in[6];
    const float* bn1_b = (const float*)d_in[7];
    const float* bn1_m = (const float*)d_in[8];
    const float* bn1_v = (const float*)d_in[9];
    const float* w_up  = (const float*)d_in[10];
    const float* bn2_g = (const float*)d_in[11];
    const float* bn2_b = (const float*)d_in[12];
    const float* bn2_m = (const float*)d_in[13];
    const float* bn2_v = (const float*)d_in[14];
    float* out = (float*)d_out;

    __half *vh, *h1h, *Wh, *Bomh, *B2h;
    float *om, *biasom;
    cudaGetSymbolAddress((void**)&vh,     g_vh);
    cudaGetSymbolAddress((void**)&h1h,    g_h1h);
    cudaGetSymbolAddress((void**)&om,     g_offmask);
    cudaGetSymbolAddress((void**)&biasom, g_biasom);
    cudaGetSymbolAddress((void**)&Wh,     g_Wh);
    cudaGetSymbolAddress((void**)&Bomh,   g_Bomh);
    cudaGetSymbolAddress((void**)&B2h,    g_B2h);

    const int STAGE0 = 17408 + 32 * 144;          // 22016 (N=32)
    const int STAGE128 = 17408 + 128 * 144;       // 35840 (N=128)
    const int smem0 = 2 * STAGE0;                 // 44032
    const int smem128 = 2 * STAGE128;             // 71680
    cudaFuncSetAttribute(mma_gemm<32, 1, 0>,
                         cudaFuncAttributeMaxDynamicSharedMemorySize, smem0);
    cudaFuncSetAttribute(mma_gemm<128, 0, 1>,
                         cudaFuncAttributeMaxDynamicSharedMemorySize, smem128);
    cudaFuncSetAttribute(mma_gemm<128, 2, 2>,
                         cudaFuncAttributeMaxDynamicSharedMemorySize, smem128);

    // weight packing
    pack_w_kernel<<<4096, 256>>>(w_reg, w_off, b_off, w_mod, b_mod, w_up);

    // stage 0: offset/mask conv (im2col fused into GEMM A-fill)
    mma_gemm<32, 1, 0><<<dim3(1, 256), 256, smem0>>>(
        x, Bomh, om, K1, biasom, nullptr, nullptr, nullptr);

    // stage 1: deform sampling + deform GEMM (+BN1+ReLU -> fp16 h1)
    build_v_kernel<<<dim3(128, 9), 256>>>(x);
    mma_gemm<128, 0, 1><<<dim3(2, 256), 256, smem128>>>(
        vh, Wh, h1h, K1, bn1_g, bn1_b, bn1_m, bn1_v);

    // stage 2: conv-transpose from fp16 h1 (+BN2+ReLU scatter)
    mma_gemm<128, 2, 2><<<dim3(8, 256), 256, smem128>>>(
        h1h, B2h, out, K2, bn2_g, bn2_b, bn2_m, bn2_v);
}